// round 16
// baseline (speedup 1.0000x reference)
#include <cuda_runtime.h>
#include <cuda_bf16.h>
#include <cstdint>
#include <math.h>

#define BATCH 8
#define CHN 512
#define NPIX 4096
#define GROUPS 32
#define CPG 16

// ---------------- scratch (__device__ globals) -------------------------------
__device__ __nv_bfloat16 g_ht[(size_t)BATCH*NPIX*CHN];     // h^T  [b][i][c]
__device__ __nv_bfloat16 g_qt[(size_t)BATCH*NPIX*CHN];     // q^T  [b][i][c]
__device__ __nv_bfloat16 g_kt[(size_t)BATCH*NPIX*CHN];     // k^T  [b][j][c]
__device__ __nv_bfloat16 g_v [(size_t)BATCH*CHN*NPIX];     // v    [b][c][j]
__device__ __nv_bfloat16 g_ot[(size_t)BATCH*NPIX*CHN];     // o^T  [b][i][c]
__device__ __nv_bfloat16 g_attn[(size_t)BATCH*NPIX*NPIX];  // exp(logits) [b][i][j]
__device__ float         g_rsum[(size_t)BATCH*NPIX];       // row sums (atomic)
__device__ int           g_ctr[8];                         // persistent tile counters
__device__ __nv_bfloat16 g_wq[CHN*CHN];
__device__ __nv_bfloat16 g_wk[CHN*CHN];
__device__ __nv_bfloat16 g_wv[CHN*CHN];
__device__ __nv_bfloat16 g_wp[CHN*CHN];

// ---------------- helpers ------------------------------------------------------
__device__ __forceinline__ uint32_t smem_u32(const void* p) {
    uint32_t a;
    asm("{ .reg .u64 t; cvta.to.shared.u64 t, %1; cvt.u32.u64 %0, t; }" : "=r"(a) : "l"(p));
    return a;
}
__device__ __forceinline__ void cpa16(uint32_t s, const void* g) {
    asm volatile("cp.async.cg.shared.global [%0], [%1], 16;" :: "r"(s), "l"(g) : "memory");
}
#define CPA_COMMIT() asm volatile("cp.async.commit_group;" ::: "memory")
#define CPA_WAIT1()  asm volatile("cp.async.wait_group 1;" ::: "memory")
#define CPA_WAIT0()  asm volatile("cp.async.wait_group 0;" ::: "memory")

__device__ __forceinline__ void ldsm4(uint32_t addr, uint32_t& r0, uint32_t& r1,
                                      uint32_t& r2, uint32_t& r3) {
    asm volatile("ldmatrix.sync.aligned.m8n8.x4.shared.b16 {%0,%1,%2,%3}, [%4];"
                 : "=r"(r0), "=r"(r1), "=r"(r2), "=r"(r3) : "r"(addr));
}

// ---------------- unified bf16 mma.sync GEMM, persistent tiles ----------------
// C[m][n] = f(sum_k A[m][k]*B[n][k]); A,B k-contiguous; BM=128 fixed.
// mode 0: +bias_m +bias_n, bf16 out
// mode 1: +bias_m +resid, fp32 out
// mode 2: exp2(acc*scale), bf16 out, atomic row-sum into rsum
// mode 3: acc / rsum[b*NPIX+m], bf16 out
#define BM 128
#define BK 64
#define NSTAGE 3

template<int BN_T, int MINB>
__global__ void __launch_bounds__(128, MINB)
gemm_tc(const __nv_bfloat16* __restrict__ A, size_t strideA,
        const __nv_bfloat16* __restrict__ B, size_t strideB,
        const __nv_bfloat16* __restrict__ B2,
        void* __restrict__ Cv, void* __restrict__ Cv2,
        size_t strideC, int ldC,
        const float* __restrict__ bias_m,
        const float* __restrict__ bias_n,
        const float* __restrict__ bias_n2,
        const float* __restrict__ resid,
        float* __restrict__ rsum,
        float scale, int K, int mode,
        int* __restrict__ ctr, int ntx, int nty, int ntiles, int nzhalf) {
    constexpr int ABYTES = BM*128;
    constexpr int BBYTES = BN_T*128;
    constexpr int STAGE = ABYTES + BBYTES;
    constexpr int WNT = BN_T/2;        // warp N tile
    constexpr int ANC = WNT/8;         // mma n-count per warp
    constexpr int BTC = WNT/16;        // b-ldsm x4 tiles per warp (16 rows each)
    constexpr int BCP = BN_T/16;       // B copy iters

    extern __shared__ char smem[];
    __shared__ int s_tile;
    uint32_t sb = smem_u32(smem);

    int tid  = threadIdx.x;
    int wid  = tid >> 5, lane = tid & 31;
    int wm = wid >> 1;
    int wn = wid & 1;

    // per-thread ldmatrix address components (tile-independent)
    int arow = wm*64 + (lane & 15);
    int akc  = lane >> 4;
    int brow = wn*WNT + (lane & 7) + ((lane >> 4) << 3);
    int bkc  = (lane >> 3) & 1;
    int xra = arow & 7, xrb = brow & 7;

    uint32_t a_base[4], b_base[BTC], xa[4], xb[4];
    #pragma unroll
    for (int i = 0; i < 4; i++) {
        a_base[i] = (uint32_t)(arow + i*16) * 128;
        xa[i] = (uint32_t)(((i*2 + akc) ^ xra) << 4);
        xb[i] = (uint32_t)(((i*2 + bkc) ^ xrb) << 4);
    }
    #pragma unroll
    for (int i = 0; i < BTC; i++)
        b_base[i] = (uint32_t)(brow + i*16) * 128;

    int g = lane >> 2, t = lane & 3;
    int nt = K / BK;

    while (true) {
        if (tid == 0) s_tile = atomicAdd(ctr, 1);
        __syncthreads();                 // publishes s_tile; fences smem reuse
        int tile = s_tile;
        if (tile >= ntiles) return;

        int xx = tile % ntx;
        int rest = tile / ntx;
        int yy = rest % nty;
        int bz = rest / nty;

        const __nv_bfloat16* Bt = B;
        const float* bnp = bias_n;
        void* Cp = Cv;
        if (B2 && bz >= nzhalf) {        // merged alt launch (q/k)
            bz -= nzhalf;
            Bt = B2; bnp = bias_n2; Cp = Cv2;
        }
        int m0 = yy * BM;
        int n0 = xx * BN_T;
        const __nv_bfloat16* Ab = A  + (size_t)bz*strideA + (size_t)m0*K;
        const __nv_bfloat16* Bb = Bt + (size_t)bz*strideB + (size_t)n0*K;

        float acc[4][ANC][4];
        #pragma unroll
        for (int i = 0; i < 4; i++)
            #pragma unroll
            for (int j = 0; j < ANC; j++)
                #pragma unroll
                for (int r = 0; r < 4; r++) acc[i][j][r] = 0.f;

        auto copy_stage = [&](int s, int k0) {
            uint32_t ab  = sb + s*STAGE;
            uint32_t bbs = ab + ABYTES;
            #pragma unroll
            for (int i = 0; i < 8; i++) {
                int q = i*128 + tid;
                int r = q >> 3, c = q & 7;
                cpa16(ab + r*128 + ((c ^ (r & 7)) << 4), Ab + (size_t)r*K + k0 + c*8);
            }
            #pragma unroll
            for (int i = 0; i < BCP; i++) {
                int q = i*128 + tid;
                int r = q >> 3, c = q & 7;
                cpa16(bbs + r*128 + ((c ^ (r & 7)) << 4), Bb + (size_t)r*K + k0 + c*8);
            }
            CPA_COMMIT();
        };

        copy_stage(0, 0);
        copy_stage(1, BK);

        for (int it = 0; it < nt; it++) {
            if (it + 1 < nt) { CPA_WAIT1(); } else { CPA_WAIT0(); }
            __syncthreads();             // single barrier per iteration
            if (it + 2 < nt) copy_stage((it + 2) % NSTAGE, (it + 2)*BK);

            uint32_t as = sb + (it % NSTAGE)*STAGE;
            uint32_t bs = as + ABYTES;

            #pragma unroll
            for (int ks = 0; ks < 4; ks++) {
                uint32_t af[4][4], bf[ANC][2];
                #pragma unroll
                for (int am = 0; am < 4; am++)
                    ldsm4(as + a_base[am] + xa[ks], af[am][0], af[am][1], af[am][2], af[am][3]);
                #pragma unroll
                for (int bt = 0; bt < BTC; bt++)
                    ldsm4(bs + b_base[bt] + xb[ks], bf[bt*2][0], bf[bt*2][1],
                                                    bf[bt*2+1][0], bf[bt*2+1][1]);
                #pragma unroll
                for (int am = 0; am < 4; am++)
                    #pragma unroll
                    for (int an = 0; an < ANC; an++) {
                        float* c = acc[am][an];
                        asm volatile(
                            "mma.sync.aligned.m16n8k16.row.col.f32.bf16.bf16.f32 "
                            "{%0,%1,%2,%3}, {%4,%5,%6,%7}, {%8,%9}, {%0,%1,%2,%3};"
                            : "+f"(c[0]), "+f"(c[1]), "+f"(c[2]), "+f"(c[3])
                            : "r"(af[am][0]), "r"(af[am][1]), "r"(af[am][2]), "r"(af[am][3]),
                              "r"(bf[an][0]), "r"(bf[an][1]));
                    }
            }
        }

        // ---- epilogue (direct stores, R13 style) ----
        #pragma unroll
        for (int am = 0; am < 4; am++) {
            int ml = m0 + wm*64 + am*16 + g;
            int mh = ml + 8;
            float pml = 0.f, pmh = 0.f;
            if (mode == 3) {
                pml = 1.0f / rsum[(size_t)bz*NPIX + ml];
                pmh = 1.0f / rsum[(size_t)bz*NPIX + mh];
            } else if (bias_m) {
                pml = bias_m[ml]; pmh = bias_m[mh];
            }
            size_t rl = (size_t)bz*strideC + (size_t)ml*ldC;
            size_t rh = (size_t)bz*strideC + (size_t)mh*ldC;
            float s0 = 0.f, s1 = 0.f;
            #pragma unroll
            for (int an = 0; an < ANC; an++) {
                int ne = n0 + wn*WNT + an*8 + 2*t;
                float v0 = acc[am][an][0], v1 = acc[am][an][1];
                float v2 = acc[am][an][2], v3 = acc[am][an][3];
                if (mode == 0) {
                    v0 += pml; v1 += pml; v2 += pmh; v3 += pmh;
                    if (bnp) {
                        float b0 = __ldg(bnp + ne), b1 = __ldg(bnp + ne + 1);
                        v0 += b0; v1 += b1; v2 += b0; v3 += b1;
                    }
                    __nv_bfloat16* C = (__nv_bfloat16*)Cp;
                    *reinterpret_cast<__nv_bfloat162*>(C + rl + ne) =
                        __nv_bfloat162{__float2bfloat16(v0), __float2bfloat16(v1)};
                    *reinterpret_cast<__nv_bfloat162*>(C + rh + ne) =
                        __nv_bfloat162{__float2bfloat16(v2), __float2bfloat16(v3)};
                } else if (mode == 1) {
                    float* C = (float*)Cp;
                    float2 r0 = *reinterpret_cast<const float2*>(resid + rl + ne);
                    float2 r1 = *reinterpret_cast<const float2*>(resid + rh + ne);
                    *reinterpret_cast<float2*>(C + rl + ne) =
                        float2{v0 + pml + r0.x, v1 + pml + r0.y};
                    *reinterpret_cast<float2*>(C + rh + ne) =
                        float2{v2 + pmh + r1.x, v3 + pmh + r1.y};
                } else if (mode == 2) {
                    float e0 = exp2f(v0*scale), e1 = exp2f(v1*scale);
                    float e2 = exp2f(v2*scale), e3 = exp2f(v3*scale);
                    s0 += e0 + e1; s1 += e2 + e3;
                    __nv_bfloat16* C = (__nv_bfloat16*)Cp;
                    *reinterpret_cast<__nv_bfloat162*>(C + rl + ne) =
                        __nv_bfloat162{__float2bfloat16(e0), __float2bfloat16(e1)};
                    *reinterpret_cast<__nv_bfloat162*>(C + rh + ne) =
                        __nv_bfloat162{__float2bfloat16(e2), __float2bfloat16(e3)};
                } else {
                    __nv_bfloat16* C = (__nv_bfloat16*)Cp;
                    *reinterpret_cast<__nv_bfloat162*>(C + rl + ne) =
                        __nv_bfloat162{__float2bfloat16(v0*pml), __float2bfloat16(v1*pml)};
                    *reinterpret_cast<__nv_bfloat162*>(C + rh + ne) =
                        __nv_bfloat162{__float2bfloat16(v2*pmh), __float2bfloat16(v3*pmh)};
                }
            }
            if (mode == 2) {
                s0 += __shfl_xor_sync(0xffffffffu, s0, 1);
                s0 += __shfl_xor_sync(0xffffffffu, s0, 2);
                s1 += __shfl_xor_sync(0xffffffffu, s1, 1);
                s1 += __shfl_xor_sync(0xffffffffu, s1, 2);
                if (t == 0) {
                    atomicAdd(&rsum[(size_t)bz*NPIX + ml], s0);
                    atomicAdd(&rsum[(size_t)bz*NPIX + mh], s1);
                }
            }
        }
    }
}

// ---------------- fp32 -> bf16 weight convert (all 4 weights, 1 launch) -------
#define WN (CHN*CHN)
__global__ void cvt4_kernel(const float* __restrict__ s0, const float* __restrict__ s1,
                            const float* __restrict__ s2, const float* __restrict__ s3,
                            __nv_bfloat16* __restrict__ d0, __nv_bfloat16* __restrict__ d1,
                            __nv_bfloat16* __restrict__ d2, __nv_bfloat16* __restrict__ d3) {
    int i = blockIdx.x * blockDim.x + threadIdx.x;
    int sel = i >> 18;
    int off = i & (WN - 1);
    const float* s = sel == 0 ? s0 : sel == 1 ? s1 : sel == 2 ? s2 : s3;
    __nv_bfloat16* d = sel == 0 ? d0 : sel == 1 ? d1 : sel == 2 ? d2 : d3;
    d[off] = __float2bfloat16(s[off]);
}

// ---------------- GroupNorm -> h^T bf16 [b][i][c] -----------------------------
__global__ void gn_kernel(const float* __restrict__ x,
                          const float* __restrict__ w,
                          const float* __restrict__ b,
                          __nv_bfloat16* __restrict__ ht) {
    int batch = blockIdx.x >> 5;
    int grp   = blockIdx.x & 31;
    const float* xp = x + ((size_t)batch*CHN + (size_t)grp*CPG) * NPIX;
    const int GE = CPG * NPIX;
    int tid = threadIdx.x;

    float s = 0.f, ss = 0.f;
    for (int i = tid; i < GE; i += 256) {
        float v = xp[i];
        s += v; ss += v*v;
    }
    __shared__ float r1[256], r2[256];
    r1[tid] = s; r2[tid] = ss;
    __syncthreads();
    for (int st = 128; st > 0; st >>= 1) {
        if (tid < st) { r1[tid] += r1[tid+st]; r2[tid] += r2[tid+st]; }
        __syncthreads();
    }
    float mean = r1[0] / (float)GE;
    float var  = r2[0] / (float)GE - mean*mean;
    float rstd = rsqrtf(var + 1e-6f);

    float wl[CPG], bl[CPG];
    #pragma unroll
    for (int c = 0; c < CPG; c++) { wl[c] = w[grp*CPG+c]; bl[c] = b[grp*CPG+c]; }

    for (int n = tid; n < NPIX; n += 256) {
        union { __nv_bfloat16 v[CPG]; uint4 u[2]; } pk;
        #pragma unroll
        for (int c = 0; c < CPG; c++) {
            float xv = xp[(size_t)c*NPIX + n];
            pk.v[c] = __float2bfloat16((xv - mean) * rstd * wl[c] + bl[c]);
        }
        uint4* dst = reinterpret_cast<uint4*>(ht + ((size_t)batch*NPIX + n)*CHN + grp*CPG);
        dst[0] = pk.u[0]; dst[1] = pk.u[1];
    }
}

// ---------------- launch -------------------------------------------------------
extern "C" void kernel_launch(void* const* d_in, const int* in_sizes, int n_in,
                              void* d_out, int out_size) {
    const float* x    = (const float*)d_in[0];
    const float* gn_w = (const float*)d_in[1];
    const float* gn_b = (const float*)d_in[2];
    const float* q_w  = (const float*)d_in[3];
    const float* q_b  = (const float*)d_in[4];
    const float* k_w  = (const float*)d_in[5];
    const float* k_b  = (const float*)d_in[6];
    const float* v_w  = (const float*)d_in[7];
    const float* v_b  = (const float*)d_in[8];
    const float* p_w  = (const float*)d_in[9];
    const float* p_b  = (const float*)d_in[10];
    float* out = (float*)d_out;

    __nv_bfloat16 *ht, *qt, *kt, *v, *ot, *attn, *wq, *wk, *wv, *wp;
    float* rsum;
    int* ctr;
    cudaGetSymbolAddress((void**)&ht, g_ht);
    cudaGetSymbolAddress((void**)&qt, g_qt);
    cudaGetSymbolAddress((void**)&kt, g_kt);
    cudaGetSymbolAddress((void**)&v,  g_v);
    cudaGetSymbolAddress((void**)&ot, g_ot);
    cudaGetSymbolAddress((void**)&attn, g_attn);
    cudaGetSymbolAddress((void**)&rsum, g_rsum);
    cudaGetSymbolAddress((void**)&ctr, g_ctr);
    cudaGetSymbolAddress((void**)&wq, g_wq);
    cudaGetSymbolAddress((void**)&wk, g_wk);
    cudaGetSymbolAddress((void**)&wv, g_wv);
    cudaGetSymbolAddress((void**)&wp, g_wp);

    const int SM128 = NSTAGE*(BM*128 + 128*128);   // 96 KB
    const int SM64  = NSTAGE*(BM*128 +  64*128);   // 72 KB
    cudaFuncSetAttribute(gemm_tc<128,2>, cudaFuncAttributeMaxDynamicSharedMemorySize, SM128);
    cudaFuncSetAttribute(gemm_tc<64,3>,  cudaFuncAttributeMaxDynamicSharedMemorySize, SM64);

    int nsm = 148;
    cudaDeviceGetAttribute(&nsm, cudaDevAttrMultiProcessorCount, 0);
    int G2 = nsm * 2;   // <128,2> persistent grid
    int G3 = nsm * 3;   // <64,3>  persistent grid

    cvt4_kernel<<<4*WN/256, 256>>>(q_w, k_w, v_w, p_w, wq, wk, wv, wp);
    gn_kernel<<<BATCH*GROUPS, 256>>>(x, gn_w, gn_b, ht);
    cudaMemsetAsync(rsum, 0, (size_t)BATCH*NPIX*sizeof(float));
    cudaMemsetAsync(ctr, 0, 8*sizeof(int));

    size_t sHT = (size_t)NPIX*CHN;
    size_t sCN = (size_t)CHN*NPIX;
    size_t sNN = (size_t)NPIX*NPIX;

    // merged q/k: q^T,k^T [i][c] = ht @ W^T + b  (M=NPIX, N=CHN, K=CHN)
    gemm_tc<128,2><<<G2, 128, SM128>>>(ht, sHT, wq, 0, wk, qt, kt, sHT, CHN,
                                       nullptr, q_b, k_b, nullptr, nullptr,
                                       1.f, CHN, 0,
                                       ctr+0, CHN/128, NPIX/BM, (CHN/128)*(NPIX/BM)*2*BATCH, BATCH);
    // v [c][j] = Wv @ ht + vb  (M=CHN, N=NPIX, K=CHN)
    gemm_tc<64,3><<<G3, 128, SM64>>>(wv, 0, ht, sHT, nullptr, v, nullptr, sCN, NPIX,
                                     v_b, nullptr, nullptr, nullptr, nullptr,
                                     1.f, CHN, 0,
                                     ctr+1, NPIX/64, CHN/BM, (NPIX/64)*(CHN/BM)*BATCH, 0);
    // attn = exp2(scale' * q·k), atomic row sums  (M=N=NPIX, K=CHN)
    gemm_tc<128,2><<<G2, 128, SM128>>>(qt, sHT, kt, sHT, nullptr, attn, nullptr, sNN, NPIX,
                                       nullptr, nullptr, nullptr, nullptr, rsum,
                                       0.044194173824159216f * 1.4426950408889634f, CHN, 2,
                                       ctr+2, NPIX/128, NPIX/BM, (NPIX/128)*(NPIX/BM)*BATCH, 0);
    // o^T[i][c] = (attn @ v^T) / rsum[i]  (M=NPIX, N=CHN, K=NPIX)
    gemm_tc<64,3><<<G3, 128, SM64>>>(attn, sNN, v, sCN, nullptr, ot, nullptr, sHT, CHN,
                                     nullptr, nullptr, nullptr, nullptr, rsum,
                                     1.f, NPIX, 3,
                                     ctr+3, CHN/64, NPIX/BM, (CHN/64)*(NPIX/BM)*BATCH, 0);
    // out = Wp @ o^T + pb + x  (M=CHN, N=NPIX, K=CHN, fp32)
    gemm_tc<64,3><<<G3, 128, SM64>>>(wp, 0, ot, sHT, nullptr, out, nullptr, sCN, NPIX,
                                     p_b, nullptr, nullptr, x, nullptr,
                                     1.f, CHN, 1,
                                     ctr+4, NPIX/64, CHN/BM, (NPIX/64)*(CHN/BM)*BATCH, 0);
}

// round 17
// speedup vs baseline: 1.2897x; 1.2897x over previous
#include <cuda_runtime.h>
#include <cuda_bf16.h>
#include <cstdint>
#include <math.h>

#define BATCH 8
#define CHN 512
#define NPIX 4096
#define GROUPS 32
#define CPG 16

// ---------------- scratch (__device__ globals) -------------------------------
__device__ __nv_bfloat16 g_ht[(size_t)BATCH*NPIX*CHN];     // h^T  [b][i][c]
__device__ __nv_bfloat16 g_qt[(size_t)BATCH*NPIX*CHN];     // q^T  [b][i][c]
__device__ __nv_bfloat16 g_kt[(size_t)BATCH*NPIX*CHN];     // k^T  [b][j][c]
__device__ __nv_bfloat16 g_v [(size_t)BATCH*CHN*NPIX];     // v    [b][c][j]
__device__ __nv_bfloat16 g_ot[(size_t)BATCH*NPIX*CHN];     // o^T  [b][i][c]
__device__ __nv_bfloat16 g_attn[(size_t)BATCH*NPIX*NPIX];  // exp(logits) [b][i][j]
__device__ float         g_rsum[(size_t)BATCH*NPIX];       // row sums (atomic)
__device__ __nv_bfloat16 g_wq[CHN*CHN];
__device__ __nv_bfloat16 g_wk[CHN*CHN];
__device__ __nv_bfloat16 g_wv[CHN*CHN];
__device__ __nv_bfloat16 g_wp[CHN*CHN];

// ---------------- helpers ------------------------------------------------------
__device__ __forceinline__ uint32_t smem_u32(const void* p) {
    uint32_t a;
    asm("{ .reg .u64 t; cvta.to.shared.u64 t, %1; cvt.u32.u64 %0, t; }" : "=r"(a) : "l"(p));
    return a;
}
__device__ __forceinline__ void cpa16(uint32_t s, const void* g) {
    asm volatile("cp.async.cg.shared.global [%0], [%1], 16;" :: "r"(s), "l"(g) : "memory");
}
#define CPA_COMMIT() asm volatile("cp.async.commit_group;" ::: "memory")
#define CPA_WAIT1()  asm volatile("cp.async.wait_group 1;" ::: "memory")
#define CPA_WAIT0()  asm volatile("cp.async.wait_group 0;" ::: "memory")

__device__ __forceinline__ void ldsm4(uint32_t addr, uint32_t& r0, uint32_t& r1,
                                      uint32_t& r2, uint32_t& r3) {
    asm volatile("ldmatrix.sync.aligned.m8n8.x4.shared.b16 {%0,%1,%2,%3}, [%4];"
                 : "=r"(r0), "=r"(r1), "=r"(r2), "=r"(r3) : "r"(addr));
}

// ---------------- unified bf16 mma.sync GEMM (templated on BN) ----------------
// C[m][n] = f(sum_k A[m][k]*B[n][k]); A,B k-contiguous; BM=128 fixed.
// mode 0: +bias_m +bias_n, bf16 out
// mode 1: +bias_m +resid, fp32 out
// mode 2: exp2(acc*scale), bf16 out, atomic row-sum into rsum
// mode 3: acc / rsum[b*NPIX+m], bf16 out
#define BM 128
#define BK 64
#define NSTAGE 3

template<int BN_T, int MINB>
__global__ void __launch_bounds__(128, MINB)
gemm_tc(const __nv_bfloat16* __restrict__ A, size_t strideA,
        const __nv_bfloat16* __restrict__ B, size_t strideB,
        const __nv_bfloat16* __restrict__ B2,
        void* __restrict__ Cv, void* __restrict__ Cv2,
        size_t strideC, int ldC,
        const float* __restrict__ bias_m,
        const float* __restrict__ bias_n,
        const float* __restrict__ bias_n2,
        const float* __restrict__ resid,
        float* __restrict__ rsum,
        float scale, int K, int mode) {
    constexpr int ABYTES = BM*128;
    constexpr int BBYTES = BN_T*128;
    constexpr int STAGE = ABYTES + BBYTES;
    constexpr int WNT = BN_T/2;        // warp N tile
    constexpr int ANC = WNT/8;         // mma n-count per warp
    constexpr int BTC = WNT/16;        // b-ldsm x4 tiles per warp (16 rows each)
    constexpr int BCP = BN_T/16;       // B copy iters

    extern __shared__ char smem[];
    uint32_t sb = smem_u32(smem);

    int tid  = threadIdx.x;
    int wid  = tid >> 5, lane = tid & 31;
    int wm = wid >> 1;
    int wn = wid & 1;
    int bz = blockIdx.z;
    if (B2 && bz >= (int)(gridDim.z >> 1)) {      // merged alt launch (q/k)
        bz -= gridDim.z >> 1;
        B = B2; bias_n = bias_n2; Cv = Cv2;
    }
    int m0 = blockIdx.y * BM;
    int n0 = blockIdx.x * BN_T;
    const __nv_bfloat16* Ab = A + (size_t)bz*strideA + (size_t)m0*K;
    const __nv_bfloat16* Bb = B + (size_t)bz*strideB + (size_t)n0*K;

    float acc[4][ANC][4];
    #pragma unroll
    for (int i = 0; i < 4; i++)
        #pragma unroll
        for (int j = 0; j < ANC; j++)
            #pragma unroll
            for (int r = 0; r < 4; r++) acc[i][j][r] = 0.f;

    auto copy_stage = [&](int s, int k0) {
        uint32_t ab  = sb + s*STAGE;
        uint32_t bbs = ab + ABYTES;
        #pragma unroll
        for (int i = 0; i < 8; i++) {
            int q = i*128 + tid;
            int r = q >> 3, c = q & 7;
            cpa16(ab + r*128 + ((c ^ (r & 7)) << 4), Ab + (size_t)r*K + k0 + c*8);
        }
        #pragma unroll
        for (int i = 0; i < BCP; i++) {
            int q = i*128 + tid;
            int r = q >> 3, c = q & 7;
            cpa16(bbs + r*128 + ((c ^ (r & 7)) << 4), Bb + (size_t)r*K + k0 + c*8);
        }
        CPA_COMMIT();
    };

    int nt = K / BK;
    copy_stage(0, 0);
    copy_stage(1, BK);

    int arow = wm*64 + (lane & 15);
    int akc  = lane >> 4;
    int brow = wn*WNT + (lane & 7) + ((lane >> 4) << 3);
    int bkc  = (lane >> 3) & 1;
    int xra = arow & 7, xrb = brow & 7;

    uint32_t a_base[4], b_base[BTC], xa[4], xb[4];
    #pragma unroll
    for (int i = 0; i < 4; i++) {
        a_base[i] = (uint32_t)(arow + i*16) * 128;
        xa[i] = (uint32_t)(((i*2 + akc) ^ xra) << 4);
        xb[i] = (uint32_t)(((i*2 + bkc) ^ xrb) << 4);
    }
    #pragma unroll
    for (int i = 0; i < BTC; i++)
        b_base[i] = (uint32_t)(brow + i*16) * 128;

    for (int it = 0; it < nt; it++) {
        if (it + 1 < nt) { CPA_WAIT1(); } else { CPA_WAIT0(); }
        __syncthreads();                         // single barrier per iteration
        if (it + 2 < nt) copy_stage((it + 2) % NSTAGE, (it + 2)*BK);

        uint32_t as = sb + (it % NSTAGE)*STAGE;
        uint32_t bs = as + ABYTES;

        #pragma unroll
        for (int ks = 0; ks < 4; ks++) {
            uint32_t af[4][4], bf[ANC][2];
            #pragma unroll
            for (int am = 0; am < 4; am++)
                ldsm4(as + a_base[am] + xa[ks], af[am][0], af[am][1], af[am][2], af[am][3]);
            #pragma unroll
            for (int bt = 0; bt < BTC; bt++)
                ldsm4(bs + b_base[bt] + xb[ks], bf[bt*2][0], bf[bt*2][1],
                                                bf[bt*2+1][0], bf[bt*2+1][1]);
            #pragma unroll
            for (int am = 0; am < 4; am++)
                #pragma unroll
                for (int an = 0; an < ANC; an++) {
                    float* c = acc[am][an];
                    asm volatile(
                        "mma.sync.aligned.m16n8k16.row.col.f32.bf16.bf16.f32 "
                        "{%0,%1,%2,%3}, {%4,%5,%6,%7}, {%8,%9}, {%0,%1,%2,%3};"
                        : "+f"(c[0]), "+f"(c[1]), "+f"(c[2]), "+f"(c[3])
                        : "r"(af[am][0]), "r"(af[am][1]), "r"(af[am][2]), "r"(af[am][3]),
                          "r"(bf[an][0]), "r"(bf[an][1]));
                }
        }
    }

    // ---- epilogue ----
    int g = lane >> 2, t = lane & 3;
    #pragma unroll
    for (int am = 0; am < 4; am++) {
        int ml = m0 + wm*64 + am*16 + g;
        int mh = ml + 8;
        float pml = 0.f, pmh = 0.f;
        if (mode == 3) {
            pml = 1.0f / rsum[(size_t)bz*NPIX + ml];
            pmh = 1.0f / rsum[(size_t)bz*NPIX + mh];
        } else if (bias_m) {
            pml = bias_m[ml]; pmh = bias_m[mh];
        }
        size_t rl = (size_t)bz*strideC + (size_t)ml*ldC;
        size_t rh = (size_t)bz*strideC + (size_t)mh*ldC;
        float s0 = 0.f, s1 = 0.f;
        #pragma unroll
        for (int an = 0; an < ANC; an++) {
            int ne = n0 + wn*WNT + an*8 + 2*t;
            float v0 = acc[am][an][0], v1 = acc[am][an][1];
            float v2 = acc[am][an][2], v3 = acc[am][an][3];
            if (mode == 0) {
                v0 += pml; v1 += pml; v2 += pmh; v3 += pmh;
                if (bias_n) {
                    float b0 = __ldg(bias_n + ne), b1 = __ldg(bias_n + ne + 1);
                    v0 += b0; v1 += b1; v2 += b0; v3 += b1;
                }
                __nv_bfloat16* C = (__nv_bfloat16*)Cv;
                *reinterpret_cast<__nv_bfloat162*>(C + rl + ne) =
                    __nv_bfloat162{__float2bfloat16(v0), __float2bfloat16(v1)};
                *reinterpret_cast<__nv_bfloat162*>(C + rh + ne) =
                    __nv_bfloat162{__float2bfloat16(v2), __float2bfloat16(v3)};
            } else if (mode == 1) {
                float* C = (float*)Cv;
                float2 r0 = *reinterpret_cast<const float2*>(resid + rl + ne);
                float2 r1 = *reinterpret_cast<const float2*>(resid + rh + ne);
                *reinterpret_cast<float2*>(C + rl + ne) =
                    float2{v0 + pml + r0.x, v1 + pml + r0.y};
                *reinterpret_cast<float2*>(C + rh + ne) =
                    float2{v2 + pmh + r1.x, v3 + pmh + r1.y};
            } else if (mode == 2) {
                float e0 = exp2f(v0*scale), e1 = exp2f(v1*scale);
                float e2 = exp2f(v2*scale), e3 = exp2f(v3*scale);
                s0 += e0 + e1; s1 += e2 + e3;
                __nv_bfloat16* C = (__nv_bfloat16*)Cv;
                *reinterpret_cast<__nv_bfloat162*>(C + rl + ne) =
                    __nv_bfloat162{__float2bfloat16(e0), __float2bfloat16(e1)};
                *reinterpret_cast<__nv_bfloat162*>(C + rh + ne) =
                    __nv_bfloat162{__float2bfloat16(e2), __float2bfloat16(e3)};
            } else {
                __nv_bfloat16* C = (__nv_bfloat16*)Cv;
                *reinterpret_cast<__nv_bfloat162*>(C + rl + ne) =
                    __nv_bfloat162{__float2bfloat16(v0*pml), __float2bfloat16(v1*pml)};
                *reinterpret_cast<__nv_bfloat162*>(C + rh + ne) =
                    __nv_bfloat162{__float2bfloat16(v2*pmh), __float2bfloat16(v3*pmh)};
            }
        }
        if (mode == 2) {   // reduce partial row sums over t-lanes, atomic once
            s0 += __shfl_xor_sync(0xffffffffu, s0, 1);
            s0 += __shfl_xor_sync(0xffffffffu, s0, 2);
            s1 += __shfl_xor_sync(0xffffffffu, s1, 1);
            s1 += __shfl_xor_sync(0xffffffffu, s1, 2);
            if (t == 0) {
                atomicAdd(&rsum[(size_t)bz*NPIX + ml], s0);
                atomicAdd(&rsum[(size_t)bz*NPIX + mh], s1);
            }
        }
    }
}

// ---------------- fp32 -> bf16 weight convert (all 4 weights, 1 launch) -------
#define WN (CHN*CHN)
__global__ void cvt4_kernel(const float* __restrict__ s0, const float* __restrict__ s1,
                            const float* __restrict__ s2, const float* __restrict__ s3,
                            __nv_bfloat16* __restrict__ d0, __nv_bfloat16* __restrict__ d1,
                            __nv_bfloat16* __restrict__ d2, __nv_bfloat16* __restrict__ d3) {
    int i = blockIdx.x * blockDim.x + threadIdx.x;
    int sel = i >> 18;
    int off = i & (WN - 1);
    const float* s = sel == 0 ? s0 : sel == 1 ? s1 : sel == 2 ? s2 : s3;
    __nv_bfloat16* d = sel == 0 ? d0 : sel == 1 ? d1 : sel == 2 ? d2 : d3;
    d[off] = __float2bfloat16(s[off]);
}

// ---------------- GroupNorm -> h^T bf16 [b][i][c] -----------------------------
__global__ void gn_kernel(const float* __restrict__ x,
                          const float* __restrict__ w,
                          const float* __restrict__ b,
                          __nv_bfloat16* __restrict__ ht) {
    int batch = blockIdx.x >> 5;
    int grp   = blockIdx.x & 31;
    const float* xp = x + ((size_t)batch*CHN + (size_t)grp*CPG) * NPIX;
    const int GE = CPG * NPIX;
    int tid = threadIdx.x;

    float s = 0.f, ss = 0.f;
    for (int i = tid; i < GE; i += 256) {
        float v = xp[i];
        s += v; ss += v*v;
    }
    __shared__ float r1[256], r2[256];
    r1[tid] = s; r2[tid] = ss;
    __syncthreads();
    for (int st = 128; st > 0; st >>= 1) {
        if (tid < st) { r1[tid] += r1[tid+st]; r2[tid] += r2[tid+st]; }
        __syncthreads();
    }
    float mean = r1[0] / (float)GE;
    float var  = r2[0] / (float)GE - mean*mean;
    float rstd = rsqrtf(var + 1e-6f);

    float wl[CPG], bl[CPG];
    #pragma unroll
    for (int c = 0; c < CPG; c++) { wl[c] = w[grp*CPG+c]; bl[c] = b[grp*CPG+c]; }

    for (int n = tid; n < NPIX; n += 256) {
        union { __nv_bfloat16 v[CPG]; uint4 u[2]; } pk;
        #pragma unroll
        for (int c = 0; c < CPG; c++) {
            float xv = xp[(size_t)c*NPIX + n];
            pk.v[c] = __float2bfloat16((xv - mean) * rstd * wl[c] + bl[c]);
        }
        uint4* dst = reinterpret_cast<uint4*>(ht + ((size_t)batch*NPIX + n)*CHN + grp*CPG);
        dst[0] = pk.u[0]; dst[1] = pk.u[1];
    }
}

// ---------------- launch -------------------------------------------------------
extern "C" void kernel_launch(void* const* d_in, const int* in_sizes, int n_in,
                              void* d_out, int out_size) {
    const float* x    = (const float*)d_in[0];
    const float* gn_w = (const float*)d_in[1];
    const float* gn_b = (const float*)d_in[2];
    const float* q_w  = (const float*)d_in[3];
    const float* q_b  = (const float*)d_in[4];
    const float* k_w  = (const float*)d_in[5];
    const float* k_b  = (const float*)d_in[6];
    const float* v_w  = (const float*)d_in[7];
    const float* v_b  = (const float*)d_in[8];
    const float* p_w  = (const float*)d_in[9];
    const float* p_b  = (const float*)d_in[10];
    float* out = (float*)d_out;

    __nv_bfloat16 *ht, *qt, *kt, *v, *ot, *attn, *wq, *wk, *wv, *wp;
    float* rsum;
    cudaGetSymbolAddress((void**)&ht, g_ht);
    cudaGetSymbolAddress((void**)&qt, g_qt);
    cudaGetSymbolAddress((void**)&kt, g_kt);
    cudaGetSymbolAddress((void**)&v,  g_v);
    cudaGetSymbolAddress((void**)&ot, g_ot);
    cudaGetSymbolAddress((void**)&attn, g_attn);
    cudaGetSymbolAddress((void**)&rsum, g_rsum);
    cudaGetSymbolAddress((void**)&wq, g_wq);
    cudaGetSymbolAddress((void**)&wk, g_wk);
    cudaGetSymbolAddress((void**)&wv, g_wv);
    cudaGetSymbolAddress((void**)&wp, g_wp);

    const int SM128 = NSTAGE*(BM*128 + 128*128);   // 96 KB
    const int SM64  = NSTAGE*(BM*128 +  64*128);   // 72 KB
    cudaFuncSetAttribute(gemm_tc<128,2>, cudaFuncAttributeMaxDynamicSharedMemorySize, SM128);
    cudaFuncSetAttribute(gemm_tc<64,3>,  cudaFuncAttributeMaxDynamicSharedMemorySize, SM64);

    // side stream + events (created outside capture semantics; not captured)
    cudaStream_t s2;
    cudaStreamCreateWithFlags(&s2, cudaStreamNonBlocking);
    cudaEvent_t e_gn, e_v;
    cudaEventCreateWithFlags(&e_gn, cudaEventDisableTiming);
    cudaEventCreateWithFlags(&e_v,  cudaEventDisableTiming);

    cvt4_kernel<<<4*WN/256, 256>>>(q_w, k_w, v_w, p_w, wq, wk, wv, wp);
    gn_kernel<<<BATCH*GROUPS, 256>>>(x, gn_w, gn_b, ht);
    cudaMemsetAsync(rsum, 0, (size_t)BATCH*NPIX*sizeof(float));
    cudaEventRecord(e_gn, 0);

    size_t sHT = (size_t)NPIX*CHN;
    size_t sCN = (size_t)CHN*NPIX;
    size_t sNN = (size_t)NPIX*NPIX;

    // side stream: v [c][j] = Wv @ ht + vb  (independent of q/k/logits)
    cudaStreamWaitEvent(s2, e_gn, 0);
    dim3 vgrid(NPIX/64, CHN/BM, BATCH);
    gemm_tc<64,3><<<vgrid, 128, SM64, s2>>>(wv, 0, ht, sHT, nullptr, v, nullptr, sCN, NPIX,
                                            v_b, nullptr, nullptr, nullptr, nullptr,
                                            1.f, CHN, 0);
    cudaEventRecord(e_v, s2);

    // main stream: merged q/k conv  (M=NPIX, N=CHN, K=CHN)
    dim3 qkgrid(CHN/128, NPIX/BM, 2*BATCH);
    gemm_tc<128,2><<<qkgrid, 128, SM128>>>(ht, sHT, wq, 0, wk, qt, kt, sHT, CHN,
                                           nullptr, q_b, k_b, nullptr, nullptr,
                                           1.f, CHN, 0);
    // attn = exp2(scale' * q·k), atomic row sums  (M=N=NPIX, K=CHN)
    dim3 lgrid(NPIX/128, NPIX/BM, BATCH);
    gemm_tc<128,2><<<lgrid, 128, SM128>>>(qt, sHT, kt, sHT, nullptr, attn, nullptr, sNN, NPIX,
                                          nullptr, nullptr, nullptr, nullptr, rsum,
                                          0.044194173824159216f * 1.4426950408889634f,
                                          CHN, 2);

    // join: out needs v + attn + rsum
    cudaStreamWaitEvent(0, e_v, 0);

    // o^T[i][c] = (attn @ v^T) / rsum[i]  (M=NPIX, N=CHN, K=NPIX)
    dim3 ogrid(CHN/64, NPIX/BM, BATCH);
    gemm_tc<64,3><<<ogrid, 128, SM64>>>(attn, sNN, v, sCN, nullptr, ot, nullptr, sHT, CHN,
                                        nullptr, nullptr, nullptr, nullptr, rsum,
                                        1.f, NPIX, 3);

    // out = Wp @ o^T + pb + x  (M=CHN, N=NPIX, K=CHN, fp32)
    dim3 pgrid(NPIX/64, CHN/BM, BATCH);
    gemm_tc<64,3><<<pgrid, 128, SM64>>>(wp, 0, ot, sHT, nullptr, out, nullptr, sCN, NPIX,
                                        p_b, nullptr, nullptr, x, nullptr,
                                        1.f, CHN, 1);
}